// round 10
// baseline (speedup 1.0000x reference)
#include <cuda_runtime.h>
#include <cuda_bf16.h>
#include <cstdint>

#define B_    256
#define N_    32
#define DH_   128
#define E_    496
#define KH    256     // DIM_HID
#define NO    96      // DIM_OUT
#define AOUT  12
#define ETILE 62      // edges per block
#define MR    124     // 2*ETILE real rows
#define MPAD  128     // A rows allocated (warp tiles reach row 127)
#define LDP   98      // Ps pitch (floats, even -> float2 aligned)
#define JTILE 64
#define LDW1  257

#define A_REGION (MPAD * 1024)            // 131072
#define B_REGION (NO * 1024)              // 98304
#define SMEM_EDGE (A_REGION + B_REGION)   // 229376

// -------- device scratch --------
__device__ float g_u[2u * B_ * N_ * KH];                    // [s][b][n][k]; s0 has +b1 folded
__device__ __align__(16) unsigned char g_w2i[NO * 1024];    // W2 interleaved hi/lo bf16, XOR-swizzled
__device__ int g_ef[E_], g_et[E_];

// -------- helpers --------
__device__ __forceinline__ uint32_t smem_u32(const void* p) {
    uint32_t a;
    asm("{ .reg .u64 t; cvta.to.shared.u64 t, %1; cvt.u32.u64 %0, t; }" : "=r"(a) : "l"(p));
    return a;
}
__device__ __forceinline__ void cp_async16(uint32_t dst, const void* src) {
    asm volatile("cp.async.cg.shared.global [%0], [%1], 16;" :: "r"(dst), "l"(src) : "memory");
}
__device__ __forceinline__ void mma16816(float* c,
                                         uint32_t a0, uint32_t a1, uint32_t a2, uint32_t a3,
                                         uint32_t b0, uint32_t b1) {
    asm volatile(
        "mma.sync.aligned.m16n8k16.row.col.f32.bf16.bf16.f32 "
        "{%0,%1,%2,%3}, {%4,%5,%6,%7}, {%8,%9}, {%0,%1,%2,%3};"
        : "+f"(c[0]), "+f"(c[1]), "+f"(c[2]), "+f"(c[3])
        : "r"(a0), "r"(a1), "r"(a2), "r"(a3), "r"(b0), "r"(b1));
}
__device__ __forceinline__ uint32_t pkbf(float hi1, float hi0) {
    return ((uint32_t)__bfloat16_as_ushort(__float2bfloat16(hi1)) << 16) |
           __bfloat16_as_ushort(__float2bfloat16(hi0));
}

// -------- prep: normalize edge dtype (int32 vs int64) --------
__global__ void prep_edges(const int* __restrict__ efw, const int* __restrict__ etw) {
    int bad = 0;
    for (int t = threadIdx.x; t < E_; t += blockDim.x)
        if (t & 1)
            if (efw[t] != 0 || etw[t] != 0) bad = 1;
    int is32 = __syncthreads_or(bad);
    for (int e = threadIdx.x; e < E_; e += blockDim.x) {
        g_ef[e] = is32 ? efw[e] : efw[2 * e];
        g_et[e] = is32 ? etw[e] : etw[2 * e];
    }
}

// -------- prep: W2 -> interleaved hi/lo bf16 cells, XOR-swizzled --------
__global__ void prep_w2(const float* __restrict__ W2) {
    int idx = blockIdx.x * 256 + threadIdx.x;    // n*256 + k
    if (idx >= NO * KH) return;
    int n = idx >> 8, k = idx & 255;
    float v = W2[idx];
    __nv_bfloat16 hi = __float2bfloat16(v);
    __nv_bfloat16 lo = __float2bfloat16(v - __bfloat162float(hi));
    uint32_t kp   = (uint32_t)(k >> 1);
    uint32_t phys = kp ^ (((uint32_t)n & 3u) << 2);
    uint32_t cell = (uint32_t)n * 1024 + phys * 8 + (uint32_t)(k & 1) * 2;
    *(__nv_bfloat16*)(g_w2i + cell)     = hi;
    *(__nv_bfloat16*)(g_w2i + cell + 4) = lo;
}

// -------- stage A: node projections (b1 folded into u1 plane) --------
__global__ void __launch_bounds__(256) node_proj(const float* __restrict__ h,
                                                 const float* __restrict__ W1,
                                                 const float* __restrict__ b1) {
    extern __shared__ float smf[];
    float* hsA = smf;                   // 32*128
    float* w1s = smf + N_ * DH_;        // 64*LDW1

    int b  = blockIdx.y;
    int j0 = blockIdx.x * JTILE;
    int tid = threadIdx.x;

    for (int i = tid; i < N_ * DH_; i += 256)
        hsA[i] = h[(size_t)b * N_ * DH_ + i];
    for (int i = tid; i < JTILE * 256; i += 256) {
        int r = i >> 8, c = i & 255;
        w1s[r * LDW1 + c] = W1[(size_t)(j0 + r) * 256 + c];
    }
    __syncthreads();

    int jl = tid & 63;
    int ng = tid >> 6;
    float acc1[8], acc2[8];
#pragma unroll
    for (int i = 0; i < 8; i++) { acc1[i] = 0.f; acc2[i] = 0.f; }

    const float* w1row = &w1s[jl * LDW1];
    const float* hbase = &hsA[ng * 8 * DH_];
#pragma unroll 4
    for (int k = 0; k < DH_; k++) {
        float wa = w1row[k];
        float wb = w1row[k + 128];
#pragma unroll
        for (int nn = 0; nn < 8; nn++) {
            float hv = hbase[nn * DH_ + k];
            acc1[nn] = fmaf(wa, hv, acc1[nn]);
            acc2[nn] = fmaf(wb, hv, acc2[nn]);
        }
    }
    int j = j0 + jl;
    float b1v = b1[j];
#pragma unroll
    for (int nn = 0; nn < 8; nn++) {
        int n = ng * 8 + nn;
        g_u[(size_t)(b * N_ + n) * KH + j] = acc1[nn] + b1v;
        g_u[(size_t)B_ * N_ * KH + (size_t)(b * N_ + n) * KH + j] = acc2[nn];
    }
}

// -------- stage B: HMMA bf16x3 GEMM, staged via cp.async + direct-L2 build --------
__global__ void __launch_bounds__(512, 1) edge_gemm(const float* __restrict__ b2,
                                                    float* __restrict__ out) {
    extern __shared__ unsigned char sm[];
    unsigned char* Asm = sm;                    // MPAD rows x 1024B (hi/lo interleaved, swizzled)
    unsigned char* Bsm = sm + A_REGION;         // NO rows x 1024B (swizzled)
    float* Ps  = (float*)Asm;                   // P result reuses A region post-MMA

    __shared__ int s_ef[ETILE], s_et[ETILE];
    __shared__ float s_b2[NO];

    int b = blockIdx.y, e0 = blockIdx.x * ETILE;
    int tid = threadIdx.x;
    int wid = tid >> 5, lid = tid & 31;

    // ---- kick off B copy (pre-swizzled, flat 96KB) via cp.async ----
    {
        uint32_t bdst = smem_u32(Bsm) + (uint32_t)tid * 16;
        const unsigned char* bsrc = g_w2i + (uint32_t)tid * 16;
#pragma unroll
        for (int i = 0; i < B_REGION / (512 * 16); i++) {
            cp_async16(bdst + i * 512 * 16, bsrc + i * 512 * 16);
        }
        asm volatile("cp.async.commit_group;" ::: "memory");
    }

    if (tid < ETILE) { s_ef[tid] = g_ef[e0 + tid]; s_et[tid] = g_et[e0 + tid]; }
    if (tid >= 128 && tid < 128 + NO) s_b2[tid - 128] = b2[tid - 128];
    __syncthreads();    // edge indices visible

    // ---- build A directly from g_u (L2): relu(u1+u2) -> interleaved hi/lo, swizzled ----
    const float* u1b = g_u + (size_t)b * N_ * KH;
    const float* u2b = g_u + (size_t)B_ * N_ * KH + (size_t)b * N_ * KH;
    // items: MR rows x 64 kq-cells (4 k each)
#pragma unroll 2
    for (int i = tid; i < MR * 64; i += 512) {
        int m = i >> 6, kq = i & 63;
        int el = (m < ETILE) ? m : m - ETILE;
        int nf, nt;
        if (m < ETILE) { nf = s_ef[el]; nt = s_et[el]; }
        else           { nf = s_et[el]; nt = s_ef[el]; }
        float4 ua = *(const float4*)(u1b + nf * KH + kq * 4);
        float4 ub = *(const float4*)(u2b + nt * KH + kq * 4);
        float v0 = fmaxf(ua.x + ub.x, 0.f), v1 = fmaxf(ua.y + ub.y, 0.f);
        float v2 = fmaxf(ua.z + ub.z, 0.f), v3 = fmaxf(ua.w + ub.w, 0.f);
        __nv_bfloat16 h0 = __float2bfloat16(v0), h1 = __float2bfloat16(v1);
        __nv_bfloat16 h2 = __float2bfloat16(v2), h3 = __float2bfloat16(v3);
        uint4 cell;
        cell.x = ((uint32_t)__bfloat16_as_ushort(h1) << 16) | __bfloat16_as_ushort(h0);
        cell.z = ((uint32_t)__bfloat16_as_ushort(h3) << 16) | __bfloat16_as_ushort(h2);
        cell.y = pkbf(v1 - __bfloat162float(h1), v0 - __bfloat162float(h0));
        cell.w = pkbf(v3 - __bfloat162float(h3), v2 - __bfloat162float(h2));
        uint32_t phys = ((uint32_t)(kq << 1)) ^ (((uint32_t)m & 3u) << 2);
        *(uint4*)(Asm + (uint32_t)m * 1024 + phys * 8) = cell;
    }
    asm volatile("cp.async.wait_group 0;" ::: "memory");
    __syncthreads();

    // ---- HMMA: 16 warps, warp tile m32 x n24, full K=256, double-buffered ----
    int m0 = (wid >> 2) * 32;
    int n0 = (wid & 3) * 24;
    int lr = lid >> 2;              // 0..7
    int lc = lid & 3;               // 0..3
    uint32_t x4 = ((uint32_t)lr & 3u) << 2;
    uint32_t q  = (uint32_t)lc | (x4 & 4u);
    uint32_t x8 = x4 & 8u;

    const unsigned char* arow0 = Asm + (uint32_t)(m0 + lr) * 1024;
    const unsigned char* arow1 = arow0 + 8 * 1024;
    const unsigned char* arow2 = arow0 + 16 * 1024;
    const unsigned char* arow3 = arow0 + 24 * 1024;
    const unsigned char* brow0 = Bsm + (uint32_t)(n0 + lr) * 1024;
    const unsigned char* brow1 = brow0 + 8 * 1024;
    const unsigned char* brow2 = brow0 + 16 * 1024;

    float acc[2][3][4];
#pragma unroll
    for (int fr = 0; fr < 2; fr++)
#pragma unroll
        for (int t = 0; t < 3; t++)
#pragma unroll
            for (int c = 0; c < 4; c++) acc[fr][t][c] = 0.f;

    uint2 Af[2][8];
    uint2 Bf[2][6];

#define LOAD_FRAGS(buf, st_) do {                                              \
        uint32_t off0 = ((((uint32_t)(st_) << 3) ^ x8) | q) << 3;              \
        uint32_t off4 = off0 ^ 32u;                                            \
        Af[buf][0] = *(const uint2*)(arow0 + off0);                            \
        Af[buf][1] = *(const uint2*)(arow1 + off0);                            \
        Af[buf][2] = *(const uint2*)(arow0 + off4);                            \
        Af[buf][3] = *(const uint2*)(arow1 + off4);                            \
        Af[buf][4] = *(const uint2*)(arow2 + off0);                            \
        Af[buf][5] = *(const uint2*)(arow3 + off0);                            \
        Af[buf][6] = *(const uint2*)(arow2 + off4);                            \
        Af[buf][7] = *(const uint2*)(arow3 + off4);                            \
        Bf[buf][0] = *(const uint2*)(brow0 + off0);                            \
        Bf[buf][1] = *(const uint2*)(brow0 + off4);                            \
        Bf[buf][2] = *(const uint2*)(brow1 + off0);                            \
        Bf[buf][3] = *(const uint2*)(brow1 + off4);                            \
        Bf[buf][4] = *(const uint2*)(brow2 + off0);                            \
        Bf[buf][5] = *(const uint2*)(brow2 + off4);                            \
    } while (0)

    LOAD_FRAGS(0, 0);
#pragma unroll
    for (int st = 0; st < 16; st++) {
        int cur = st & 1;
        if (st < 15) LOAD_FRAGS(cur ^ 1, st + 1);
#pragma unroll
        for (int fr = 0; fr < 2; fr++) {
            uint2 a0 = Af[cur][fr * 4 + 0];
            uint2 a1 = Af[cur][fr * 4 + 1];
            uint2 a2 = Af[cur][fr * 4 + 2];
            uint2 a3 = Af[cur][fr * 4 + 3];
#pragma unroll
            for (int t = 0; t < 3; t++) {
                uint2 b0 = Bf[cur][t * 2 + 0];
                uint2 b1 = Bf[cur][t * 2 + 1];
                mma16816(acc[fr][t], a0.x, a1.x, a2.x, a3.x, b0.x, b1.x);
                mma16816(acc[fr][t], a0.y, a1.y, a2.y, a3.y, b0.x, b1.x);
                mma16816(acc[fr][t], a0.x, a1.x, a2.x, a3.x, b0.y, b1.y);
            }
        }
    }
#undef LOAD_FRAGS

    __syncthreads();    // all smem reads of A/B done before Ps overwrite

    // ---- epilogue: direct store acc (+b2) into Ps ----
#pragma unroll
    for (int fr = 0; fr < 2; fr++) {
#pragma unroll
        for (int t = 0; t < 3; t++) {
            int mrow = m0 + fr * 16 + lr;
            int col  = n0 + t * 8 + lc * 2;
            float bx = s_b2[col], by = s_b2[col + 1];
            if (mrow < MR)
                *(float2*)(Ps + mrow * LDP + col) =
                    make_float2(acc[fr][t][0] + bx, acc[fr][t][1] + by);
            if (mrow + 8 < MR)
                *(float2*)(Ps + (mrow + 8) * LDP + col) =
                    make_float2(acc[fr][t][2] + bx, acc[fr][t][3] + by);
        }
    }
    __syncthreads();

    // ---- payoff ----
    for (int pr = tid; pr < ETILE * AOUT; pr += 512) {
        int el = pr / AOUT;
        int i  = pr - el * AOUT;
        const float* P0 = &Ps[el * LDP];
        const float* P1 = &Ps[(ETILE + el) * LDP];
        float a0[4], a1[4];
#pragma unroll
        for (int r = 0; r < 4; r++) {
            a0[r] = P0[24 * r + i];
            a1[r] = P1[24 * r + 12 + i];
        }
        float res[12];
#pragma unroll
        for (int j = 0; j < 12; j++) {
            float s = 0.f;
#pragma unroll
            for (int r = 0; r < 4; r++)
                s = fmaf(a0[r], P0[24 * r + 12 + j], fmaf(a1[r], P1[24 * r + j], s));
            res[j] = 0.5f * s;
        }
        float4* op = reinterpret_cast<float4*>(
            out + ((size_t)(b * E_ + e0 + el) * AOUT + i) * AOUT);
        op[0] = make_float4(res[0], res[1], res[2],  res[3]);
        op[1] = make_float4(res[4], res[5], res[6],  res[7]);
        op[2] = make_float4(res[8], res[9], res[10], res[11]);
    }
}

// -------- launch --------
extern "C" void kernel_launch(void* const* d_in, const int* in_sizes, int n_in,
                              void* d_out, int out_size) {
    const float* h  = (const float*)d_in[0];
    const float* W1 = (const float*)d_in[1];
    const float* b1 = (const float*)d_in[2];
    const float* W2 = (const float*)d_in[3];
    const float* b2 = (const float*)d_in[4];
    const int*   ef = (const int*)d_in[5];
    const int*   et = (const int*)d_in[6];
    float* out = (float*)d_out;

    const int SMEM_A = (N_ * DH_ + JTILE * LDW1) * 4;      // 82,176 B

    cudaFuncSetAttribute(node_proj, cudaFuncAttributeMaxDynamicSharedMemorySize, SMEM_A);
    cudaFuncSetAttribute(edge_gemm, cudaFuncAttributeMaxDynamicSharedMemorySize, SMEM_EDGE);

    prep_edges<<<1, 256>>>(ef, et);
    prep_w2<<<(NO * KH + 255) / 256, 256>>>(W2);
    node_proj<<<dim3(KH / JTILE, B_), 256, SMEM_A>>>(h, W1, b1);
    edge_gemm<<<dim3(E_ / ETILE, B_), 512, SMEM_EDGE>>>(b2, out);
}